// round 14
// baseline (speedup 1.0000x reference)
#include <cuda_runtime.h>
#include <cuda_fp16.h>
#include <math_constants.h>

#define D      128
#define BGR    512
#define NWARP  8
#define NTHR   256
#define KW     256          // GEMM K (= 2*D)
#define GCOLS  512          // GEMM output cols (4 gates x 128 features, interleaved)
#define STG    3            // per-warp cp.async ring depth
#define GRP    4            // nodes per stage
#define SPLIT  2            // attention split-K per graph
#define GRUA_BLKS 64        // embedded h-half GEMM blocks (64x64 tiles)
#define MAXN   204800       // fp16 x-cache capacity (nodes)
#define LOG2E  1.4426950408889634f

// init kernel block-range sizes
#define PREP_BLKS  512      // GCOLS*KW / 256
#define BIAS_BLKS  256      // BGR*D / 256

// ---------------- device scratch (no allocation allowed) ----------------
__device__ float   g_h[BGR * D];            // hidden state (current)
__device__ float   g_Wbig[GCOLS * KW];      // merged weights, col 4f+g
__device__ float   g_bias[GCOLS];           // merged biases [br,bz,bin,bhn] per feature
__device__ int     g_starts[BGR + 1];       // segment boundaries (batch is sorted)
__device__ float   g_acc[BGR * GCOLS];      // h-half GEMM partials (1MB)
__device__ float   g_pm[BGR * SPLIT];       // split partial max (base-2 logits)
__device__ float   g_ps[BGR * SPLIT];       // split partial sum
__device__ float   g_prr[BGR * SPLIT][D];   // split partial unnormalized r
__device__ __half  g_xh[(size_t)MAXN * D];  // fp16 copy of x (52MB), built in pass 0

__device__ __forceinline__ float sigf(float v) { return 1.f / (1.f + __expf(-v)); }
__device__ __forceinline__ float ex2f(float v) {
    float r; asm("ex2.approx.f32 %0, %1;" : "=f"(r) : "f"(v)); return r;
}

__device__ __forceinline__ void cp16(void* sdst, const void* gsrc) {
    unsigned s = (unsigned)__cvta_generic_to_shared(sdst);
    asm volatile("cp.async.cg.shared.global [%0], [%1], 16;" :: "r"(s), "l"(gsrc));
}
__device__ __forceinline__ void cp8(void* sdst, const void* gsrc) {
    unsigned s = (unsigned)__cvta_generic_to_shared(sdst);
    asm volatile("cp.async.ca.shared.global [%0], [%1], 8;" :: "r"(s), "l"(gsrc));
}
__device__ __forceinline__ void cp_commit() { asm volatile("cp.async.commit_group;"); }
template<int N> __device__ __forceinline__ void cp_wait() {
    asm volatile("cp.async.wait_group %0;" :: "n"(N));
}

// batch may be delivered as int32 or int64; sniff layout from a mid element.
__device__ __forceinline__ bool batch_is_i64(const void* bp, int N) {
    long long v = ((const long long*)bp)[N >> 2];
    return (v >= 0 && v < BGR);
}
__device__ __forceinline__ int batch_at(const void* bp, int i, bool is64) {
    int v = is64 ? (int)((const long long*)bp)[i] : ((const int*)bp)[i];
    return min(max(v, 0), BGR - 1);
}

// ---------------- fused init: prep (Wbig/bias) + step-1 h + segment starts -------------
__global__ void init_kernel(const void* __restrict__ batch, int N,
                            const float* __restrict__ W_ih, const float* __restrict__ W_hh,
                            const float* __restrict__ b_ih, const float* __restrict__ b_hh) {
    int bx = blockIdx.x;
    int t  = threadIdx.x;

    if (bx < PREP_BLKS) {
        int idx = bx * 256 + t;                 // < GCOLS*KW
        int c = idx >> 8;
        int k = idx & (KW - 1);
        int f = c >> 2, g = c & 3;
        float v;
        if (g == 0)      v = W_ih[(size_t)f * KW + k]         + (k < D ? W_hh[(size_t)f * D + k] : 0.f);
        else if (g == 1) v = W_ih[(size_t)(D + f) * KW + k]   + (k < D ? W_hh[(size_t)(D + f) * D + k] : 0.f);
        else if (g == 2) v = W_ih[(size_t)(2 * D + f) * KW + k];
        else             v = (k < D) ? W_hh[(size_t)(2 * D + f) * D + k] : 0.f;
        g_Wbig[(size_t)c * KW + k] = v;
        if (k == 0) {
            float b;
            if (g == 0)      b = b_ih[f] + b_hh[f];
            else if (g == 1) b = b_ih[D + f] + b_hh[D + f];
            else if (g == 2) b = b_ih[2 * D + f];
            else             b = b_hh[2 * D + f];
            g_bias[c] = b;
        }
    } else if (bx < PREP_BLKS + BIAS_BLKS) {
        int idx = (bx - PREP_BLKS) * 256 + t;   // < BGR*D
        int f = idx & (D - 1);
        float r = sigf(b_ih[f] + b_hh[f]);
        float z = sigf(b_ih[D + f] + b_hh[D + f]);
        float n = tanhf(b_ih[2 * D + f] + r * b_hh[2 * D + f]);
        g_h[idx] = (1.f - z) * n;
    } else {
        int i = (bx - PREP_BLKS - BIAS_BLKS) * 256 + t;
        if (i >= N) return;
        bool is64 = batch_is_i64(batch, N);
        int bi = batch_at(batch, i, is64);
        if (i == 0) {
            for (int b = 0; b <= bi; b++) g_starts[b] = 0;
        } else {
            int bp = batch_at(batch, i - 1, is64);
            for (int b = bp + 1; b <= bi; b++) g_starts[b] = i;
        }
        if (i == N - 1) {
            for (int b = bi + 1; b <= BGR; b++) g_starts[b] = N;
        }
    }
}

// ---------------- per-row merge coefficients (splits -> normalized weights) -------------
__device__ __forceinline__ void merge_coefs(int row, float& k0, float& k1) {
    float m0 = g_pm[2 * row], m1 = g_pm[2 * row + 1];
    float M = fmaxf(m0, m1);
    if (M == -CUDART_INF_F) { k0 = 0.f; k1 = 0.f; return; }   // empty graph
    float c0 = ex2f(m0 - M), c1 = ex2f(m1 - M);
    float inv = 1.f / (c0 * g_ps[2 * row] + c1 * g_ps[2 * row + 1] + 1e-16f);
    k0 = c0 * inv; k1 = c1 * inv;
}

// ---------------- gruB: split-merge + r-half GEMM + gate epilogue ----------------------
#define GKT 16
__global__ void __launch_bounds__(128) grub_kernel(const float* __restrict__ q_star) {
    __shared__ __align__(16) float As[GKT][32];
    __shared__ __align__(16) float Ws[GKT][64];
    __shared__ float kc0[32], kc1[32];

    int t  = threadIdx.x;
    int tx = t & 15;
    int ty = t >> 4;           // 0..7 -> 4 rows each
    int r0 = blockIdx.y * 32;
    int c0 = blockIdx.x * 64;

    if (t < 32) merge_coefs(r0 + t, kc0[t], kc1[t]);

    float acc[4][4];
#pragma unroll
    for (int i = 0; i < 4; i++)
        *(float4*)acc[i] = *(const float4*)(g_acc + (size_t)(r0 + ty * 4 + i) * GCOLS + c0 + tx * 4);
    __syncthreads();           // kc ready

    for (int k0 = 0; k0 < D; k0 += GKT) {
        {   // A tile 32r x 16k: merged r = kc0*rr0 + kc1*rr1
            int row = t >> 2, k = (t & 3) << 2;
            float a0 = kc0[row], a1 = kc1[row];
            float4 v0 = *(const float4*)&g_prr[2 * (r0 + row)][k0 + k];
            float4 v1 = *(const float4*)&g_prr[2 * (r0 + row) + 1][k0 + k];
            As[k][row]     = v0.x * a0 + v1.x * a1;
            As[k + 1][row] = v0.y * a0 + v1.y * a1;
            As[k + 2][row] = v0.z * a0 + v1.z * a1;
            As[k + 3][row] = v0.w * a0 + v1.w * a1;
        }
        {   // W tile 64c x 16k from Wbig k in [128,256)
            int col = t >> 1, k = (t & 1) << 3;
            const float* wp = g_Wbig + (size_t)(c0 + col) * KW + D + k0 + k;
            float4 v0 = *(const float4*)wp;
            float4 v1 = *(const float4*)(wp + 4);
            Ws[k][col]     = v0.x; Ws[k + 1][col] = v0.y; Ws[k + 2][col] = v0.z; Ws[k + 3][col] = v0.w;
            Ws[k + 4][col] = v1.x; Ws[k + 5][col] = v1.y; Ws[k + 6][col] = v1.z; Ws[k + 7][col] = v1.w;
        }
        __syncthreads();
#pragma unroll
        for (int kk = 0; kk < GKT; kk++) {
            float a[4], w[4];
            *(float4*)a = *(const float4*)&As[kk][ty * 4];
            *(float4*)w = *(const float4*)&Ws[kk][tx * 4];
#pragma unroll
            for (int i = 0; i < 4; i++) {
#pragma unroll
                for (int j = 0; j < 4; j++) acc[i][j] += a[i] * w[j];
            }
        }
        __syncthreads();
    }

    int f = (c0 >> 2) + tx;
    float4 gb = *(const float4*)&g_bias[4 * f];   // [br, bz, bin, bhn]
#pragma unroll
    for (int i = 0; i < 4; i++) {
        int row = r0 + ty * 4 + i;
        float hold = q_star[(size_t)row * KW + f];    // h_old = q half of q_star
        float r = sigf(acc[i][0] + gb.x);
        float z = sigf(acc[i][1] + gb.y);
        float n = tanhf(acc[i][2] + gb.z + r * (acc[i][3] + gb.w));
        g_h[(size_t)row * D + f] = (1.f - z) * n + z * hold;
    }
}

// ---------------- final merge: write output r into q_star ------------------------------
__global__ void __launch_bounds__(D) merge_kernel(float* __restrict__ q_star) {
    int b = blockIdx.x;
    int t = threadIdx.x;
    __shared__ float k0s, k1s;
    if (t == 0) merge_coefs(b, k0s, k1s);
    __syncthreads();
    q_star[(size_t)b * KW + D + t] = k0s * g_prr[2 * b][t] + k1s * g_prr[2 * b + 1][t];
}

// ---------------- gruA block body (shared by both attn kernels) ------------------------
__device__ __forceinline__ void gruA_block(int gb, float* smem, int t) {
    int r0 = (gb & 7) * 64;
    int c0 = (gb >> 3) * 64;
    float* As = smem;                // [16][64]
    float* Ws = smem + GKT * 64;     // [16][64]
    int tx = t & 15, ty = t >> 4;    // 16x16 threads, 4x4 each
    float acc[4][4] = {};

    for (int k0 = 0; k0 < D; k0 += GKT) {
        {
            int row = t >> 2, k = (t & 3) << 2;
            float4 v = *(const float4*)(g_h + (size_t)(r0 + row) * D + k0 + k);
            As[(k) * 64 + row] = v.x; As[(k + 1) * 64 + row] = v.y;
            As[(k + 2) * 64 + row] = v.z; As[(k + 3) * 64 + row] = v.w;
        }
        {
            int col = t >> 2, k = (t & 3) << 2;
            float4 v = *(const float4*)(g_Wbig + (size_t)(c0 + col) * KW + k0 + k);
            Ws[(k) * 64 + col] = v.x; Ws[(k + 1) * 64 + col] = v.y;
            Ws[(k + 2) * 64 + col] = v.z; Ws[(k + 3) * 64 + col] = v.w;
        }
        __syncthreads();
#pragma unroll
        for (int kk = 0; kk < GKT; kk++) {
            float a[4], w[4];
            *(float4*)a = *(const float4*)&As[kk * 64 + ty * 4];
            *(float4*)w = *(const float4*)&Ws[kk * 64 + tx * 4];
#pragma unroll
            for (int i = 0; i < 4; i++) {
#pragma unroll
                for (int j = 0; j < 4; j++) acc[i][j] += a[i] * w[j];
            }
        }
        __syncthreads();
    }
#pragma unroll
    for (int i = 0; i < 4; i++)
        *(float4*)(g_acc + (size_t)(r0 + ty * 4 + i) * GCOLS + c0 + tx * 4) = *(float4*)acc[i];
}

// ---------------- attention epilogue: write split partials -----------------------------
__device__ __forceinline__ void attn_epilogue(int pidx, int t, int warp, int lane,
                                              float m, float s, float4 racc,
                                              float* wm, float* wsum, float (*wr)[D]) {
    if (lane == 0) { wm[warp] = m; wsum[warp] = s; }
    *(float4*)(&wr[warp][lane * 4]) = racc;
    __syncthreads();
    if (t < D) {
        float mb = wm[0];
#pragma unroll
        for (int w = 1; w < NWARP; w++) mb = fmaxf(mb, wm[w]);
        float stot = 0.f, rf = 0.f;
#pragma unroll
        for (int w = 0; w < NWARP; w++) {
            float c = ex2f(wm[w] - mb);   // 0 for warps that saw no node (wm=-inf)
            stot += c * wsum[w];
            rf   += c * wr[w][t];
        }
        g_prr[pidx][t] = rf;
        if (t == 0) { g_pm[pidx] = mb; g_ps[pidx] = stot; }
    }
}

// shared attention prologue: split range + q load (scaled), q-half write, empty handling
#define ATTN_PROLOGUE                                                              \
    int b  = blockIdx.x >> 1;                                                      \
    int sp = blockIdx.x & 1;                                                       \
    int pidx = 2 * b + sp;                                                         \
    int gs = g_starts[b], ge = g_starts[b + 1], glen = ge - gs;                    \
    int start = gs + ((glen * sp) >> 1);                                           \
    int end   = gs + ((glen * (sp + 1)) >> 1);                                     \
    int warp = t >> 5;                                                             \
    int lane = t & 31;                                                             \
    if (t < D) {                                                                   \
        float qv = g_h[(size_t)b * D + t];                                         \
        q_s[t] = qv * LOG2E;                 /* base-2 logits */                   \
        q_star[(size_t)b * KW + t] = qv;     /* q half (both splits, same val) */  \
    }                                                                              \
    __syncthreads();                                                               \
    if (start >= end) {                      /* empty split */                     \
        if (t < D) g_prr[pidx][t] = 0.f;                                           \
        if (t == 0) { g_pm[pidx] = -CUDART_INF_F; g_ps[pidx] = 0.f; }              \
        return;                                                                    \
    }                                                                              \
    const int stride = NWARP * GRP;                                                \
    int base0 = start + warp * GRP;                                                \
    int last  = end - 1;                                                           \
    int ngrp  = (base0 < end) ? (end - base0 + stride - 1) / stride : 0;

// ---------------- attention pass 0: f32 x, fp16 cache store, split-K --------------------
__global__ void __launch_bounds__(NTHR) attn_f32_kernel(const float* __restrict__ x,
                                                        float* __restrict__ q_star,
                                                        int do_store) {
    __shared__ __align__(16) float smem_buf[NWARP * STG * GRP * D];   // 48KB
    __shared__ __align__(16) float q_s[D];
    __shared__ float wm[NWARP], wsum[NWARP];
    __shared__ __align__(16) float wr[NWARP][D];

    int t = threadIdx.x;
    if (blockIdx.x >= BGR * SPLIT) { gruA_block(blockIdx.x - BGR * SPLIT, smem_buf, t); return; }

    float (*xs)[STG][GRP][D] = (float(*)[STG][GRP][D])smem_buf;
    ATTN_PROLOGUE

#pragma unroll
    for (int i = 0; i < STG; i++) {
        int gbase = base0 + i * stride;
        if (i < ngrp) {
#pragma unroll
            for (int j = 0; j < GRP; j++) {
                int node = min(gbase + j, last);
                cp16(&xs[warp][i][j][lane * 4], x + (size_t)node * D + lane * 4);
            }
        }
        cp_commit();
    }

    float4 qf = *(const float4*)(q_s + lane * 4);
    float m = -CUDART_INF_F;
    float s = 0.f;
    float4 racc = make_float4(0.f, 0.f, 0.f, 0.f);

    for (int gi = 0; gi < ngrp; gi++) {
        cp_wait<STG - 1>();
        __syncwarp();

        int slot = gi % STG;
        int gbase = base0 + gi * stride;
        float4 xv[GRP];
        float  d[GRP];
#pragma unroll
        for (int j = 0; j < GRP; j++) {
            xv[j] = *(const float4*)&xs[warp][slot][j][lane * 4];
            d[j] = xv[j].x * qf.x + xv[j].y * qf.y + xv[j].z * qf.z + xv[j].w * qf.w;
        }
        if (do_store) {                 // build fp16 x-cache for later passes
#pragma unroll
            for (int j = 0; j < GRP; j++) {
                int node = gbase + j;
                if (node < end) {
                    __half2 p0 = __floats2half2_rn(xv[j].x, xv[j].y);
                    __half2 p1 = __floats2half2_rn(xv[j].z, xv[j].w);
                    uint2 u;
                    u.x = *(unsigned*)&p0;
                    u.y = *(unsigned*)&p1;
                    *(uint2*)(&g_xh[(size_t)node * D + lane * 4]) = u;
                }
            }
        }
#pragma unroll
        for (int off = 16; off >= 1; off >>= 1) {
#pragma unroll
            for (int j = 0; j < GRP; j++) d[j] += __shfl_xor_sync(0xffffffffu, d[j], off);
        }
#pragma unroll
        for (int j = 0; j < GRP; j++) {
            if (gbase + j >= end) break;
            if (d[j] <= m) {
                float w = ex2f(d[j] - m);
                s += w;
                racc.x += w * xv[j].x; racc.y += w * xv[j].y;
                racc.z += w * xv[j].z; racc.w += w * xv[j].w;
            } else {
                float sc = ex2f(m - d[j]);
                m = d[j];
                s = s * sc + 1.f;
                racc.x = racc.x * sc + xv[j].x; racc.y = racc.y * sc + xv[j].y;
                racc.z = racc.z * sc + xv[j].z; racc.w = racc.w * sc + xv[j].w;
            }
        }
        __syncwarp();

        int nb = base0 + (gi + STG) * stride;
        if (gi + STG < ngrp) {
#pragma unroll
            for (int j = 0; j < GRP; j++) {
                int node = min(nb + j, last);
                cp16(&xs[warp][slot][j][lane * 4], x + (size_t)node * D + lane * 4);
            }
        }
        cp_commit();
    }

    attn_epilogue(pidx, t, warp, lane, m, s, racc, wm, wsum, wr);
}

// ---------------- attention passes 1-2: fp16 x-cache, split-K ---------------------------
__global__ void __launch_bounds__(NTHR) attn_f16_kernel(float* __restrict__ q_star) {
    __shared__ __align__(16) float smem_buf[NWARP * STG * GRP * (D / 2)];  // 24KB halfs
    __shared__ __align__(16) float q_s[D];
    __shared__ float wm[NWARP], wsum[NWARP];
    __shared__ __align__(16) float wr[NWARP][D];

    int t = threadIdx.x;
    if (blockIdx.x >= BGR * SPLIT) { gruA_block(blockIdx.x - BGR * SPLIT, smem_buf, t); return; }

    __half (*xs)[STG][GRP][D] = (__half(*)[STG][GRP][D])smem_buf;
    ATTN_PROLOGUE

#pragma unroll
    for (int i = 0; i < STG; i++) {
        int gbase = base0 + i * stride;
        if (i < ngrp) {
#pragma unroll
            for (int j = 0; j < GRP; j++) {
                int node = min(gbase + j, last);
                cp8(&xs[warp][i][j][lane * 4], &g_xh[(size_t)node * D + lane * 4]);
            }
        }
        cp_commit();
    }

    float4 qf = *(const float4*)(q_s + lane * 4);
    float m = -CUDART_INF_F;
    float s = 0.f;
    float4 racc = make_float4(0.f, 0.f, 0.f, 0.f);

    for (int gi = 0; gi < ngrp; gi++) {
        cp_wait<STG - 1>();
        __syncwarp();

        int slot = gi % STG;
        int gbase = base0 + gi * stride;
        float4 xv[GRP];
        float  d[GRP];
#pragma unroll
        for (int j = 0; j < GRP; j++) {
            uint2 u = *(const uint2*)&xs[warp][slot][j][lane * 4];
            float2 fa = __half22float2(*(__half2*)&u.x);
            float2 fb = __half22float2(*(__half2*)&u.y);
            xv[j] = make_float4(fa.x, fa.y, fb.x, fb.y);
            d[j] = xv[j].x * qf.x + xv[j].y * qf.y + xv[j].z * qf.z + xv[j].w * qf.w;
        }
#pragma unroll
        for (int off = 16; off >= 1; off >>= 1) {
#pragma unroll
            for (int j = 0; j < GRP; j++) d[j] += __shfl_xor_sync(0xffffffffu, d[j], off);
        }
#pragma unroll
        for (int j = 0; j < GRP; j++) {
            if (gbase + j >= end) break;
            if (d[j] <= m) {
                float w = ex2f(d[j] - m);
                s += w;
                racc.x += w * xv[j].x; racc.y += w * xv[j].y;
                racc.z += w * xv[j].z; racc.w += w * xv[j].w;
            } else {
                float sc = ex2f(m - d[j]);
                m = d[j];
                s = s * sc + 1.f;
                racc.x = racc.x * sc + xv[j].x; racc.y = racc.y * sc + xv[j].y;
                racc.z = racc.z * sc + xv[j].z; racc.w = racc.w * sc + xv[j].w;
            }
        }
        __syncwarp();

        int nb = base0 + (gi + STG) * stride;
        if (gi + STG < ngrp) {
#pragma unroll
            for (int j = 0; j < GRP; j++) {
                int node = min(nb + j, last);
                cp8(&xs[warp][slot][j][lane * 4], &g_xh[(size_t)node * D + lane * 4]);
            }
        }
        cp_commit();
    }

    attn_epilogue(pidx, t, warp, lane, m, s, racc, wm, wsum, wr);
}

// ---------------- launch ----------------
extern "C" void kernel_launch(void* const* d_in, const int* in_sizes, int n_in,
                              void* d_out, int out_size) {
    const float* x     = (const float*)d_in[0];
    const void*  batch = d_in[1];
    int base = (n_in >= 7) ? 3 : 2;    // d_in[2] may be the batch_size scalar
    const float* W_ih = (const float*)d_in[base];
    const float* W_hh = (const float*)d_in[base + 1];
    const float* b_ih = (const float*)d_in[base + 2];
    const float* b_hh = (const float*)d_in[base + 3];

    float* q_star = (float*)d_out;     // [BGR, 2D]
    int N = in_sizes[0] / D;
    int uh = (N <= MAXN) ? 1 : 0;      // fp16 cache fits?

    int init_blocks = PREP_BLKS + BIAS_BLKS + (N + 255) / 256;
    init_kernel<<<init_blocks, 256>>>(batch, N, W_ih, W_hh, b_ih, b_hh);

    dim3 bgrid(GCOLS / 64, BGR / 32);                 // 128 blocks for grub
    const int AG = BGR * SPLIT + GRUA_BLKS;           // 1088: attn splits + gruA

    // pass 1 (q = h1): f32 read + fp16 cache store; gruA(h1) embedded
    attn_f32_kernel<<<AG, NTHR>>>(x, q_star, uh);
    grub_kernel<<<bgrid, 128>>>(q_star);              // -> h2

    // pass 2 (q = h2): fp16 read; gruA(h2) embedded
    if (uh) attn_f16_kernel<<<AG, NTHR>>>(q_star);
    else    attn_f32_kernel<<<AG, NTHR>>>(x, q_star, 0);
    grub_kernel<<<bgrid, 128>>>(q_star);              // -> h3

    // pass 3 (q = h3): fp16 read, no gruA; then final merge writes output r
    if (uh) attn_f16_kernel<<<BGR * SPLIT, NTHR>>>(q_star);
    else    attn_f32_kernel<<<BGR * SPLIT, NTHR>>>(x, q_star, 0);
    merge_kernel<<<BGR, D>>>(q_star);
}